// round 13
// baseline (speedup 1.0000x reference)
#include <cuda_runtime.h>
#include <cuda_fp16.h>
#include <math.h>

// Problem dims
#define Bv 64
#define Tv 512
#define Iv 128
#define Hv 1024
#define Gv 4096          // 4*H
#define BTv (Bv*Tv)      // 32768

#define NBLK 128         // persistent CTAs for recurrence

// ---------------------------------------------------------------------------
// Static device scratch
// ---------------------------------------------------------------------------
__device__ float g_xg[(size_t)BTv * Gv];       // [B,T,4H] gate pre-activations
__device__ float g_bias0[Gv];
__device__ float g_bias1[Gv];

// fp16 activations
__device__ __half g_xf[(size_t)BTv * Iv];      // x in fp16
__device__ __half g_h1f[(size_t)BTv * Hv];
__device__ __half g_h2f[(size_t)BTv * Hv];

// fp16 hi/lo weights, [c = 4j+q][k] layout
__device__ __half g_Wi0h[(size_t)Gv * Iv];     // W_ih0
__device__ __half g_Wi0l[(size_t)Gv * Iv];
__device__ __half g_Wfh[(size_t)Gv * Hv];      // W_ih1
__device__ __half g_Wfl[(size_t)Gv * Hv];
__device__ __half g_W0h[(size_t)Gv * Hv];      // W_hh0
__device__ __half g_W0l[(size_t)Gv * Hv];
__device__ __half g_W1h[(size_t)Gv * Hv];      // W_hh1
__device__ __half g_W1l[(size_t)Gv * Hv];

// h0 fp16: [2][64][1024]
__device__ __half g_h0s[2 * Bv * Hv];

// software grid barrier
__device__ unsigned g_bar_count = 0;
__device__ volatile unsigned g_bar_gen = 0;

__device__ __forceinline__ void grid_barrier(unsigned& local_gen)
{
    __threadfence();
    __syncthreads();
    if (threadIdx.x == 0) {
        unsigned gen = local_gen;
        if (atomicAdd(&g_bar_count, 1u) == NBLK - 1) {
            g_bar_count = 0;
            __threadfence();
            g_bar_gen = gen + 1;
        } else {
            while (g_bar_gen == gen) { }
        }
        __threadfence();
    }
    __syncthreads();
    local_gen++;
}

// ---------------------------------------------------------------------------
// HMMA / ldmatrix / cp.async helpers
// ---------------------------------------------------------------------------
__device__ __forceinline__ unsigned smem_u32(const void* p)
{
    unsigned a;
    asm("{ .reg .u64 t; cvta.to.shared.u64 t, %1; cvt.u32.u64 %0, t; }"
        : "=r"(a) : "l"(p));
    return a;
}
__device__ __forceinline__ void ldm_x4(unsigned r[4], unsigned addr)
{
    asm volatile("ldmatrix.sync.aligned.m8n8.x4.shared.b16 {%0,%1,%2,%3}, [%4];"
                 : "=r"(r[0]), "=r"(r[1]), "=r"(r[2]), "=r"(r[3]) : "r"(addr));
}
__device__ __forceinline__ void ldm_x2(unsigned r[2], unsigned addr)
{
    asm volatile("ldmatrix.sync.aligned.m8n8.x2.shared.b16 {%0,%1}, [%2];"
                 : "=r"(r[0]), "=r"(r[1]) : "r"(addr));
}
__device__ __forceinline__ void mma16816f(float d[4], const unsigned a[4], const unsigned b[2])
{
    asm volatile("mma.sync.aligned.m16n8k16.row.col.f32.f16.f16.f32 "
                 "{%0,%1,%2,%3}, {%4,%5,%6,%7}, {%8,%9}, {%0,%1,%2,%3};"
                 : "+f"(d[0]), "+f"(d[1]), "+f"(d[2]), "+f"(d[3])
                 : "r"(a[0]), "r"(a[1]), "r"(a[2]), "r"(a[3]), "r"(b[0]), "r"(b[1]));
}
__device__ __forceinline__ void cp16(unsigned dst, const void* src)
{
    asm volatile("cp.async.cg.shared.global [%0], [%1], 16;"
                 :: "r"(dst), "l"(src) : "memory");
}
#define CP_COMMIT() asm volatile("cp.async.commit_group;" ::: "memory")
#define CP_WAIT4()  asm volatile("cp.async.wait_group 4;" ::: "memory")
#define CP_WAIT3()  asm volatile("cp.async.wait_group 3;" ::: "memory")
#define CP_WAIT2()  asm volatile("cp.async.wait_group 2;" ::: "memory")
#define CP_WAIT1()  asm volatile("cp.async.wait_group 1;" ::: "memory")
#define CP_WAIT0()  asm volatile("cp.async.wait_group 0;" ::: "memory")

__device__ __forceinline__ float sigf(float v) { return 1.0f / (1.0f + expf(-v)); }

// ---------------------------------------------------------------------------
// Prep: weight transforms (fp16 hi/lo) + x/h0 fp16.
// ---------------------------------------------------------------------------
__global__ void prep_kernel(const float* __restrict__ Whh0, const float* __restrict__ Whh1,
                            const float* __restrict__ Wih0, const float* __restrict__ Wih1,
                            const float* __restrict__ bih0, const float* __restrict__ bhh0,
                            const float* __restrict__ bih1, const float* __restrict__ bhh1,
                            const float* __restrict__ h0,   const float* __restrict__ x)
{
    size_t stride = (size_t)gridDim.x * blockDim.x;
    size_t tid0 = (size_t)blockIdx.x * blockDim.x + threadIdx.x;

    for (size_t s = tid0; s < (size_t)Gv * Hv; s += stride) {
        int row = (int)(s >> 10);
        int k   = (int)(s & 1023);
        int q = row >> 10;
        int j = row & 1023;
        size_t bdst = (size_t)(4 * j + q) * Hv + k;

        float v = Whh0[s];
        __half hi = __float2half_rn(v);
        g_W0h[bdst] = hi;
        g_W0l[bdst] = __float2half_rn(v - __half2float(hi));

        v = Whh1[s];
        hi = __float2half_rn(v);
        g_W1h[bdst] = hi;
        g_W1l[bdst] = __float2half_rn(v - __half2float(hi));

        v = Wih1[s];
        hi = __float2half_rn(v);
        g_Wfh[bdst] = hi;
        g_Wfl[bdst] = __float2half_rn(v - __half2float(hi));
    }
    for (size_t s = tid0; s < (size_t)Gv * Iv; s += stride) {
        int row = (int)(s >> 7);
        int k   = (int)(s & 127);
        int q = row >> 10;
        int j = row & 1023;
        size_t bdst = (size_t)(4 * j + q) * Iv + k;
        float v = Wih0[s];
        __half hi = __float2half_rn(v);
        g_Wi0h[bdst] = hi;
        g_Wi0l[bdst] = __float2half_rn(v - __half2float(hi));
    }
    for (size_t s = tid0; s < (size_t)Gv; s += stride) {
        int q = (int)(s >> 10);
        int j = (int)(s & 1023);
        g_bias0[4 * j + q] = bih0[s] + bhh0[s];
        g_bias1[4 * j + q] = bih1[s] + bhh1[s];
    }
    for (size_t s = tid0; s < (size_t)2 * Bv * Hv; s += stride) {
        g_h0s[s] = __float2half_rn(h0[s]);
    }
    for (size_t s = tid0; s < (size_t)BTv * Iv; s += stride) {
        g_xf[s] = __float2half_rn(x[s]);
    }
}

// ---------------------------------------------------------------------------
// Projection GEMM via fp16 HMMA (A single, W hi/lo). Template K; globals
// selected in DEVICE code (never pass __device__ symbols as kernel args!).
// CTA: 128 bt x 128 gate cols. K chunked by 32, 2-stage cp.async pipeline.
// ---------------------------------------------------------------------------
#define PJ_ROWB 80
#define PJ_MAT  (128 * PJ_ROWB)
#define PJ_STAGE (3 * PJ_MAT)        // A | Bh | Bl = 30720 B
#define PJ_SMEM  (2 * PJ_STAGE)      // 61440 B

template <int K>
__device__ __forceinline__ void pj_load_chunk(unsigned sbase, int bt0, int n0, int k0, int tid)
{
    const __half* __restrict__ A  = (K == Iv) ? g_xf   : g_h1f;
    const __half* __restrict__ Bh = (K == Iv) ? g_Wi0h : g_Wfh;
    const __half* __restrict__ Bl = (K == Iv) ? g_Wi0l : g_Wfl;
#pragma unroll
    for (int i = 0; i < 6; i++) {
        int u = tid + 256 * i;       // 0..1535
        int mat = u >> 9;            // 0..2
        int rr  = (u >> 2) & 127;
        int cc  = u & 3;
        unsigned dst = sbase + mat * PJ_MAT + rr * PJ_ROWB + cc * 16;
        const __half* src;
        if      (mat == 0) src = A  + (size_t)(bt0 + rr) * K + k0 + cc * 8;
        else if (mat == 1) src = Bh + (size_t)(n0  + rr) * K + k0 + cc * 8;
        else               src = Bl + (size_t)(n0  + rr) * K + k0 + cc * 8;
        cp16(dst, src);
    }
}

template <int K>
__global__ void __launch_bounds__(256, 2)
proj_mma_kernel()
{
    extern __shared__ char dsm[];
    unsigned sb0 = smem_u32(dsm);

    __shared__ float s_bias[128];

    const float* __restrict__ bias = (K == Iv) ? g_bias0 : g_bias1;
    const int NCHUNK = K / 32;

    int tid  = threadIdx.x;
    int lane = tid & 31;
    int w    = tid >> 5;
    int wm   = w & 1;
    int wn   = w >> 1;
    int n0   = blockIdx.x * 128;
    int bt0  = blockIdx.y * 128;

    for (int i = tid; i < 128; i += 256) s_bias[i] = bias[n0 + i];

    float acc[4][4][4];
#pragma unroll
    for (int mf = 0; mf < 4; mf++)
#pragma unroll
        for (int nf = 0; nf < 4; nf++)
#pragma unroll
            for (int e = 0; e < 4; e++) acc[mf][nf][e] = 0.f;

    unsigned aoff = (unsigned)((64 * wm + (lane & 15)) * PJ_ROWB + ((lane & 16) ? 16 : 0));
    int rl = lane & 15;
    unsigned boff = (unsigned)((32 * wn + (rl & 7)) * PJ_ROWB + ((rl & 8) ? 16 : 0));

    pj_load_chunk<K>(sb0,            bt0, n0, 0,  tid); CP_COMMIT();
    pj_load_chunk<K>(sb0 + PJ_STAGE, bt0, n0, 32, tid); CP_COMMIT();

    for (int c = 0; c < NCHUNK; c++) {
        unsigned sb = sb0 + (c & 1) * PJ_STAGE;
        if (c < NCHUNK - 1) { CP_WAIT1(); } else { CP_WAIT0(); }
        __syncthreads();

#pragma unroll
        for (int ks = 0; ks < 2; ks++) {
            unsigned kb = (unsigned)(ks * 32);
            unsigned Ahf[4][4], Bhf[4][2], Blf[4][2];
#pragma unroll
            for (int mf = 0; mf < 4; mf++)
                ldm_x4(Ahf[mf], sb + aoff + kb + (unsigned)(16 * mf * PJ_ROWB));
#pragma unroll
            for (int nf = 0; nf < 4; nf++) {
                unsigned rb = sb + PJ_MAT + boff + kb + (unsigned)(8 * nf * PJ_ROWB);
                ldm_x2(Bhf[nf], rb);
                ldm_x2(Blf[nf], rb + PJ_MAT);
            }
#pragma unroll
            for (int mf = 0; mf < 4; mf++)
#pragma unroll
                for (int nf = 0; nf < 4; nf++) {
                    mma16816f(acc[mf][nf], Ahf[mf], Bhf[nf]);
                    mma16816f(acc[mf][nf], Ahf[mf], Blf[nf]);
                }
        }

        __syncthreads();
        if (c + 2 < NCHUNK) {
            pj_load_chunk<K>(sb, bt0, n0, (c + 2) * 32, tid);
            CP_COMMIT();
        }
    }

    int mrow = bt0 + 64 * wm + (lane >> 2);
    int ncol = 32 * wn + 2 * (lane & 3);
#pragma unroll
    for (int mf = 0; mf < 4; mf++) {
#pragma unroll
        for (int nf = 0; nf < 4; nf++) {
            int cc = ncol + 8 * nf;
            float b0 = s_bias[cc], b1 = s_bias[cc + 1];
            float* p0 = &g_xg[(size_t)(mrow + 16 * mf) * Gv + n0 + cc];
            float* p1 = &g_xg[(size_t)(mrow + 16 * mf + 8) * Gv + n0 + cc];
            *(float2*)p0 = make_float2(acc[mf][nf][0] + b0, acc[mf][nf][1] + b1);
            *(float2*)p1 = make_float2(acc[mf][nf][2] + b0, acc[mf][nf][3] + b1);
        }
    }
}

// ---------------------------------------------------------------------------
// Persistent recurrence via fp16 HMMA — round-11 structure (64-k chunks,
// pitch 144, split accumulators, register epilogue) with a SIX-stage
// cp.async pipeline (5 chunks in flight) to absorb mid-loop L2 latency.
// SMEM map (bytes):
//   0       sWh [32][1032 f16] (pitch 2064)
//   66048   sWl
//   132096  sA stages 0..5, each [64][72 f16] (9216 B)
// total 187392
// ---------------------------------------------------------------------------
#define LW_PITCHB 2064
#define LA_PITCHB 144
#define LA_STAGEB 9216
#define LS_SMEM   187392

__device__ __forceinline__ void la_load(unsigned dst, const __half* hsrc,
                                        size_t hstr, int k0, int tid)
{
#pragma unroll
    for (int i = 0; i < 2; i++) {
        int u = tid + 256 * i;       // 0..511
        int rr = u >> 3;             // 0..63
        int cc = u & 7;
        cp16(dst + rr * LA_PITCHB + cc * 16, hsrc + (size_t)rr * hstr + k0 + cc * 8);
    }
}

__global__ void __launch_bounds__(256, 1)
lstm_mma_kernel(int layer, const float* __restrict__ c0l)
{
    extern __shared__ char sm[];
    unsigned sb = smem_u32(sm);

    const __half* __restrict__ Wh = layer ? g_W1h : g_W0h;
    const __half* __restrict__ Wl = layer ? g_W1l : g_W0l;
    __half* __restrict__ seqf     = layer ? g_h2f : g_h1f;

    int tid  = threadIdx.x;
    int lane = tid & 31;
    int w    = tid >> 5;
    int n0   = blockIdx.x * 32;
    int j0   = blockIdx.x * 8;

    // one-time W load (hi/lo)
    {
        const unsigned* srcH = (const unsigned*)(Wh + (size_t)n0 * Hv);
        const unsigned* srcL = (const unsigned*)(Wl + (size_t)n0 * Hv);
        unsigned* dH = (unsigned*)sm;
        unsigned* dL = (unsigned*)(sm + 66048);
        for (int i = tid; i < 32 * 512; i += 256) {
            int r = i >> 9, cc = i & 511;
            dH[r * 516 + cc] = srcH[r * 512 + cc];
            dL[r * 516 + cc] = srcL[r * 512 + cc];
        }
    }
    __syncthreads();

    int wm = w & 1, wn = w >> 1;
    int jl = 2 * wn + ((lane & 3) >> 1);
    bool evn = ((lane & 1) == 0);

    float c_[4];
#pragma unroll
    for (int mf = 0; mf < 2; mf++)
#pragma unroll
        for (int rr = 0; rr < 2; rr++) {
            int b = 32 * wm + 16 * mf + (lane >> 2) + 8 * rr;
            c_[mf * 2 + rr] = c0l[(size_t)b * Hv + j0 + jl];
        }

    unsigned aoff  = (unsigned)((32 * wm + (lane & 15)) * LA_PITCHB + ((lane & 16) ? 16 : 0));
    int rl = lane & 15;
    unsigned boffH = sb + (unsigned)((8 * wn + (rl & 7)) * LW_PITCHB + ((rl & 8) ? 16 : 0));
    unsigned boffL = boffH + 66048;
    unsigned sAb = sb + 132096;

    unsigned lg = g_bar_gen;

    for (int t = 0; t < Tv; t++) {
        const __half* hsrc;
        size_t hstr;
        if (t == 0) {
            hsrc = g_h0s + layer * (Bv * Hv);
            hstr = Hv;
        } else {
            hsrc = seqf + (size_t)(t - 1) * Hv;
            hstr = (size_t)Tv * Hv;
        }

        // prologue: 5 chunks in flight (stages 0..4)
#pragma unroll
        for (int p = 0; p < 5; p++) {
            la_load(sAb + p * LA_STAGEB, hsrc, hstr, p * 64, tid);
            CP_COMMIT();
        }

        float4 xgv[4];
#pragma unroll
        for (int mf = 0; mf < 2; mf++)
#pragma unroll
            for (int rr = 0; rr < 2; rr++) {
                int b = 32 * wm + 16 * mf + (lane >> 2) + 8 * rr;
                xgv[mf * 2 + rr] = *(const float4*)&g_xg[((size_t)b * Tv + t) * Gv + n0 + 4 * jl];
            }

        float accH[2][4], accL[2][4];
#pragma unroll
        for (int mf = 0; mf < 2; mf++)
#pragma unroll
            for (int e = 0; e < 4; e++) { accH[mf][e] = 0.f; accL[mf][e] = 0.f; }

        for (int ch = 0; ch < 16; ch++) {
            unsigned ab = sAb + (ch % 6) * LA_STAGEB;
            // chunk ch complete when pending <= min(4, 15 - ch)
            if (ch <= 11)      { CP_WAIT4(); }
            else if (ch == 12) { CP_WAIT3(); }
            else if (ch == 13) { CP_WAIT2(); }
            else if (ch == 14) { CP_WAIT1(); }
            else               { CP_WAIT0(); }
            __syncthreads();

            if (ch + 5 < 16) {
                la_load(sAb + ((ch + 5) % 6) * LA_STAGEB, hsrc, hstr, (ch + 5) * 64, tid);
                CP_COMMIT();
            }

#pragma unroll
            for (int ks = 0; ks < 4; ks++) {
                unsigned kb = (unsigned)(ks * 32);
                unsigned wkb = (unsigned)((ch * 64 + ks * 16) * 2);
                unsigned Ahf[2][4], Bhf[2], Blf[2];
#pragma unroll
                for (int mf = 0; mf < 2; mf++)
                    ldm_x4(Ahf[mf], ab + aoff + kb + (unsigned)(16 * mf * LA_PITCHB));
                ldm_x2(Bhf, boffH + wkb);
                ldm_x2(Blf, boffL + wkb);
#pragma unroll
                for (int mf = 0; mf < 2; mf++) {
                    mma16816f(accH[mf], Ahf[mf], Bhf);
                    mma16816f(accL[mf], Ahf[mf], Blf);
                }
            }
        }

        // combine hi/lo accumulators
        float acc[2][4];
#pragma unroll
        for (int mf = 0; mf < 2; mf++)
#pragma unroll
            for (int e = 0; e < 4; e++) acc[mf][e] = accH[mf][e] + accL[mf][e];

        // register epilogue: pair lanes exchange (i,f)<->(g,o)
        float pr[2][4];
#pragma unroll
        for (int mf = 0; mf < 2; mf++)
#pragma unroll
            for (int e = 0; e < 4; e++)
                pr[mf][e] = __shfl_xor_sync(0xFFFFFFFFu, acc[mf][e], 1);

#pragma unroll
        for (int mf = 0; mf < 2; mf++) {
#pragma unroll
            for (int rr = 0; rr < 2; rr++) {
                int ci = mf * 2 + rr;
                int b = 32 * wm + 16 * mf + (lane >> 2) + 8 * rr;
                float iv, fv, gv, ov;
                if (evn) { iv = acc[mf][2 * rr]; fv = acc[mf][2 * rr + 1];
                           gv = pr[mf][2 * rr];  ov = pr[mf][2 * rr + 1]; }
                else     { iv = pr[mf][2 * rr];  fv = pr[mf][2 * rr + 1];
                           gv = acc[mf][2 * rr]; ov = acc[mf][2 * rr + 1]; }
                float4 xg = xgv[ci];
                float i_ = sigf(iv + xg.x);
                float f_ = sigf(fv + xg.y);
                float g_ = tanhf(gv + xg.z);
                float o_ = sigf(ov + xg.w);
                float c = f_ * c_[ci] + i_ * g_;
                c_[ci] = c;
                float h = o_ * tanhf(c);
                if (evn) {
                    size_t idx = ((size_t)b * Tv + t) * Hv + j0 + jl;
                    seqf[idx] = __float2half_rn(h);
                }
            }
        }

        if (t != Tv - 1) grid_barrier(lg);
    }
}

// ---------------------------------------------------------------------------
// Final FC — reads fp16 h2 directly.
// ---------------------------------------------------------------------------
__global__ void fc_kernel(const float* __restrict__ Wfc, const float* __restrict__ bfc,
                          float* __restrict__ out)
{
    int bt = blockIdx.x * 8 + (threadIdx.x >> 5);
    int lane = threadIdx.x & 31;
    const __half2* hrow = (const __half2*)(g_h2f + (size_t)bt * Hv);
    float s = 0.f;
#pragma unroll 4
    for (int k = lane; k < Hv / 2; k += 32) {
        float2 h2 = __half22float2(hrow[k]);
        s += h2.x * Wfc[2 * k] + h2.y * Wfc[2 * k + 1];
    }
#pragma unroll
    for (int off = 16; off; off >>= 1) s += __shfl_down_sync(0xFFFFFFFFu, s, off);
    if (lane == 0) out[bt] = s + bfc[0];
}

// ---------------------------------------------------------------------------
// Launch (6 graph nodes)
// ---------------------------------------------------------------------------
extern "C" void kernel_launch(void* const* d_in, const int* in_sizes, int n_in,
                              void* d_out, int out_size)
{
    (void)in_sizes; (void)n_in; (void)out_size;
    const float* x    = (const float*)d_in[0];
    const float* h0   = (const float*)d_in[1];
    const float* c0   = (const float*)d_in[2];
    const float* Wih0 = (const float*)d_in[3];
    const float* Whh0 = (const float*)d_in[4];
    const float* bih0 = (const float*)d_in[5];
    const float* bhh0 = (const float*)d_in[6];
    const float* Wih1 = (const float*)d_in[7];
    const float* Whh1 = (const float*)d_in[8];
    const float* bih1 = (const float*)d_in[9];
    const float* bhh1 = (const float*)d_in[10];
    const float* Wfc  = (const float*)d_in[11];
    const float* bfc  = (const float*)d_in[12];
    float* out = (float*)d_out;

    cudaFuncSetAttribute(lstm_mma_kernel,
                         cudaFuncAttributeMaxDynamicSharedMemorySize, LS_SMEM);
    cudaFuncSetAttribute(proj_mma_kernel<Iv>,
                         cudaFuncAttributeMaxDynamicSharedMemorySize, PJ_SMEM);
    cudaFuncSetAttribute(proj_mma_kernel<Hv>,
                         cudaFuncAttributeMaxDynamicSharedMemorySize, PJ_SMEM);

    prep_kernel<<<2048, 256>>>(Whh0, Whh1, Wih0, Wih1, bih0, bhh0, bih1, bhh1, h0, x);

    // Layer 0: HMMA projection (K=128) + recurrence
    proj_mma_kernel<Iv><<<dim3(Gv / 128, BTv / 128), 256, PJ_SMEM>>>();
    lstm_mma_kernel<<<NBLK, 256, LS_SMEM>>>(0, c0);

    // Layer 1: HMMA projection (K=1024) + recurrence
    proj_mma_kernel<Hv><<<dim3(Gv / 128, BTv / 128), 256, PJ_SMEM>>>();
    lstm_mma_kernel<<<NBLK, 256, LS_SMEM>>>(1, c0 + (size_t)Bv * Hv);

    fc_kernel<<<BTv / 8, 256>>>(Wfc, bfc, out);
}

// round 14
// speedup vs baseline: 1.5216x; 1.5216x over previous
#include <cuda_runtime.h>
#include <cuda_fp16.h>
#include <math.h>

// Problem dims
#define Bv 64
#define Tv 512
#define Iv 128
#define Hv 1024
#define Gv 4096          // 4*H
#define BTv (Bv*Tv)      // 32768

#define NBLK 128         // persistent CTAs for recurrence

// ---------------------------------------------------------------------------
// Static device scratch
// ---------------------------------------------------------------------------
__device__ float g_xg[(size_t)BTv * Gv];       // [B,T,4H] gate pre-activations
__device__ float g_bias0[Gv];
__device__ float g_bias1[Gv];

// fp16 activations
__device__ __half g_xf[(size_t)BTv * Iv];      // x in fp16
__device__ __half g_h1f[(size_t)BTv * Hv];
__device__ __half g_h2f[(size_t)BTv * Hv];

// fp16 hi/lo weights, [c = 4j+q][k] layout
__device__ __half g_Wi0h[(size_t)Gv * Iv];     // W_ih0
__device__ __half g_Wi0l[(size_t)Gv * Iv];
__device__ __half g_Wfh[(size_t)Gv * Hv];      // W_ih1
__device__ __half g_Wfl[(size_t)Gv * Hv];
__device__ __half g_W0h[(size_t)Gv * Hv];      // W_hh0
__device__ __half g_W0l[(size_t)Gv * Hv];
__device__ __half g_W1h[(size_t)Gv * Hv];      // W_hh1
__device__ __half g_W1l[(size_t)Gv * Hv];

// h0 fp16: [2][64][1024]
__device__ __half g_h0s[2 * Bv * Hv];

// software grid barrier
__device__ unsigned g_bar_count = 0;
__device__ volatile unsigned g_bar_gen = 0;

__device__ __forceinline__ void grid_barrier(unsigned& local_gen)
{
    __threadfence();
    __syncthreads();
    if (threadIdx.x == 0) {
        unsigned gen = local_gen;
        if (atomicAdd(&g_bar_count, 1u) == NBLK - 1) {
            g_bar_count = 0;
            __threadfence();
            g_bar_gen = gen + 1;
        } else {
            while (g_bar_gen == gen) { }
        }
        __threadfence();
    }
    __syncthreads();
    local_gen++;
}

// ---------------------------------------------------------------------------
// HMMA / ldmatrix / cp.async helpers
// ---------------------------------------------------------------------------
__device__ __forceinline__ unsigned smem_u32(const void* p)
{
    unsigned a;
    asm("{ .reg .u64 t; cvta.to.shared.u64 t, %1; cvt.u32.u64 %0, t; }"
        : "=r"(a) : "l"(p));
    return a;
}
__device__ __forceinline__ void ldm_x4(unsigned r[4], unsigned addr)
{
    asm volatile("ldmatrix.sync.aligned.m8n8.x4.shared.b16 {%0,%1,%2,%3}, [%4];"
                 : "=r"(r[0]), "=r"(r[1]), "=r"(r[2]), "=r"(r[3]) : "r"(addr));
}
__device__ __forceinline__ void ldm_x2(unsigned r[2], unsigned addr)
{
    asm volatile("ldmatrix.sync.aligned.m8n8.x2.shared.b16 {%0,%1}, [%2];"
                 : "=r"(r[0]), "=r"(r[1]) : "r"(addr));
}
__device__ __forceinline__ void mma16816f(float d[4], const unsigned a[4], const unsigned b[2])
{
    asm volatile("mma.sync.aligned.m16n8k16.row.col.f32.f16.f16.f32 "
                 "{%0,%1,%2,%3}, {%4,%5,%6,%7}, {%8,%9}, {%0,%1,%2,%3};"
                 : "+f"(d[0]), "+f"(d[1]), "+f"(d[2]), "+f"(d[3])
                 : "r"(a[0]), "r"(a[1]), "r"(a[2]), "r"(a[3]), "r"(b[0]), "r"(b[1]));
}
__device__ __forceinline__ void cp16(unsigned dst, const void* src)
{
    asm volatile("cp.async.cg.shared.global [%0], [%1], 16;"
                 :: "r"(dst), "l"(src) : "memory");
}
#define CP_COMMIT() asm volatile("cp.async.commit_group;" ::: "memory")
#define CP_WAIT2()  asm volatile("cp.async.wait_group 2;" ::: "memory")
#define CP_WAIT1()  asm volatile("cp.async.wait_group 1;" ::: "memory")
#define CP_WAIT0()  asm volatile("cp.async.wait_group 0;" ::: "memory")

__device__ __forceinline__ float sigf(float v) { return 1.0f / (1.0f + expf(-v)); }

// ---------------------------------------------------------------------------
// Prep: weight transforms (fp16 hi/lo) + x/h0 fp16.
// ---------------------------------------------------------------------------
__global__ void prep_kernel(const float* __restrict__ Whh0, const float* __restrict__ Whh1,
                            const float* __restrict__ Wih0, const float* __restrict__ Wih1,
                            const float* __restrict__ bih0, const float* __restrict__ bhh0,
                            const float* __restrict__ bih1, const float* __restrict__ bhh1,
                            const float* __restrict__ h0,   const float* __restrict__ x)
{
    size_t stride = (size_t)gridDim.x * blockDim.x;
    size_t tid0 = (size_t)blockIdx.x * blockDim.x + threadIdx.x;

    for (size_t s = tid0; s < (size_t)Gv * Hv; s += stride) {
        int row = (int)(s >> 10);
        int k   = (int)(s & 1023);
        int q = row >> 10;
        int j = row & 1023;
        size_t bdst = (size_t)(4 * j + q) * Hv + k;

        float v = Whh0[s];
        __half hi = __float2half_rn(v);
        g_W0h[bdst] = hi;
        g_W0l[bdst] = __float2half_rn(v - __half2float(hi));

        v = Whh1[s];
        hi = __float2half_rn(v);
        g_W1h[bdst] = hi;
        g_W1l[bdst] = __float2half_rn(v - __half2float(hi));

        v = Wih1[s];
        hi = __float2half_rn(v);
        g_Wfh[bdst] = hi;
        g_Wfl[bdst] = __float2half_rn(v - __half2float(hi));
    }
    for (size_t s = tid0; s < (size_t)Gv * Iv; s += stride) {
        int row = (int)(s >> 7);
        int k   = (int)(s & 127);
        int q = row >> 10;
        int j = row & 1023;
        size_t bdst = (size_t)(4 * j + q) * Iv + k;
        float v = Wih0[s];
        __half hi = __float2half_rn(v);
        g_Wi0h[bdst] = hi;
        g_Wi0l[bdst] = __float2half_rn(v - __half2float(hi));
    }
    for (size_t s = tid0; s < (size_t)Gv; s += stride) {
        int q = (int)(s >> 10);
        int j = (int)(s & 1023);
        g_bias0[4 * j + q] = bih0[s] + bhh0[s];
        g_bias1[4 * j + q] = bih1[s] + bhh1[s];
    }
    for (size_t s = tid0; s < (size_t)2 * Bv * Hv; s += stride) {
        g_h0s[s] = __float2half_rn(h0[s]);
    }
    for (size_t s = tid0; s < (size_t)BTv * Iv; s += stride) {
        g_xf[s] = __float2half_rn(x[s]);
    }
}

// ---------------------------------------------------------------------------
// Projection GEMM via fp16 HMMA (A single, W hi/lo). Template K; globals
// selected in DEVICE code (never pass __device__ symbols as kernel args!).
// CTA: 128 bt x 128 gate cols. K chunked by 32, 2-stage cp.async pipeline.
// ---------------------------------------------------------------------------
#define PJ_ROWB 80
#define PJ_MAT  (128 * PJ_ROWB)
#define PJ_STAGE (3 * PJ_MAT)        // A | Bh | Bl = 30720 B
#define PJ_SMEM  (2 * PJ_STAGE)      // 61440 B

template <int K>
__device__ __forceinline__ void pj_load_chunk(unsigned sbase, int bt0, int n0, int k0, int tid)
{
    const __half* __restrict__ A  = (K == Iv) ? g_xf   : g_h1f;
    const __half* __restrict__ Bh = (K == Iv) ? g_Wi0h : g_Wfh;
    const __half* __restrict__ Bl = (K == Iv) ? g_Wi0l : g_Wfl;
#pragma unroll
    for (int i = 0; i < 6; i++) {
        int u = tid + 256 * i;       // 0..1535
        int mat = u >> 9;            // 0..2
        int rr  = (u >> 2) & 127;
        int cc  = u & 3;
        unsigned dst = sbase + mat * PJ_MAT + rr * PJ_ROWB + cc * 16;
        const __half* src;
        if      (mat == 0) src = A  + (size_t)(bt0 + rr) * K + k0 + cc * 8;
        else if (mat == 1) src = Bh + (size_t)(n0  + rr) * K + k0 + cc * 8;
        else               src = Bl + (size_t)(n0  + rr) * K + k0 + cc * 8;
        cp16(dst, src);
    }
}

template <int K>
__global__ void __launch_bounds__(256, 2)
proj_mma_kernel()
{
    extern __shared__ char dsm[];
    unsigned sb0 = smem_u32(dsm);

    __shared__ float s_bias[128];

    const float* __restrict__ bias = (K == Iv) ? g_bias0 : g_bias1;
    const int NCHUNK = K / 32;

    int tid  = threadIdx.x;
    int lane = tid & 31;
    int w    = tid >> 5;
    int wm   = w & 1;
    int wn   = w >> 1;
    int n0   = blockIdx.x * 128;
    int bt0  = blockIdx.y * 128;

    for (int i = tid; i < 128; i += 256) s_bias[i] = bias[n0 + i];

    float acc[4][4][4];
#pragma unroll
    for (int mf = 0; mf < 4; mf++)
#pragma unroll
        for (int nf = 0; nf < 4; nf++)
#pragma unroll
            for (int e = 0; e < 4; e++) acc[mf][nf][e] = 0.f;

    unsigned aoff = (unsigned)((64 * wm + (lane & 15)) * PJ_ROWB + ((lane & 16) ? 16 : 0));
    int rl = lane & 15;
    unsigned boff = (unsigned)((32 * wn + (rl & 7)) * PJ_ROWB + ((rl & 8) ? 16 : 0));

    pj_load_chunk<K>(sb0,            bt0, n0, 0,  tid); CP_COMMIT();
    pj_load_chunk<K>(sb0 + PJ_STAGE, bt0, n0, 32, tid); CP_COMMIT();

    for (int c = 0; c < NCHUNK; c++) {
        unsigned sb = sb0 + (c & 1) * PJ_STAGE;
        if (c < NCHUNK - 1) { CP_WAIT1(); } else { CP_WAIT0(); }
        __syncthreads();

#pragma unroll
        for (int ks = 0; ks < 2; ks++) {
            unsigned kb = (unsigned)(ks * 32);
            unsigned Ahf[4][4], Bhf[4][2], Blf[4][2];
#pragma unroll
            for (int mf = 0; mf < 4; mf++)
                ldm_x4(Ahf[mf], sb + aoff + kb + (unsigned)(16 * mf * PJ_ROWB));
#pragma unroll
            for (int nf = 0; nf < 4; nf++) {
                unsigned rb = sb + PJ_MAT + boff + kb + (unsigned)(8 * nf * PJ_ROWB);
                ldm_x2(Bhf[nf], rb);
                ldm_x2(Blf[nf], rb + PJ_MAT);
            }
#pragma unroll
            for (int mf = 0; mf < 4; mf++)
#pragma unroll
                for (int nf = 0; nf < 4; nf++) {
                    mma16816f(acc[mf][nf], Ahf[mf], Bhf[nf]);
                    mma16816f(acc[mf][nf], Ahf[mf], Blf[nf]);
                }
        }

        __syncthreads();
        if (c + 2 < NCHUNK) {
            pj_load_chunk<K>(sb, bt0, n0, (c + 2) * 32, tid);
            CP_COMMIT();
        }
    }

    int mrow = bt0 + 64 * wm + (lane >> 2);
    int ncol = 32 * wn + 2 * (lane & 3);
#pragma unroll
    for (int mf = 0; mf < 4; mf++) {
#pragma unroll
        for (int nf = 0; nf < 4; nf++) {
            int cc = ncol + 8 * nf;
            float b0 = s_bias[cc], b1 = s_bias[cc + 1];
            float* p0 = &g_xg[(size_t)(mrow + 16 * mf) * Gv + n0 + cc];
            float* p1 = &g_xg[(size_t)(mrow + 16 * mf + 8) * Gv + n0 + cc];
            *(float2*)p0 = make_float2(acc[mf][nf][0] + b0, acc[mf][nf][1] + b1);
            *(float2*)p1 = make_float2(acc[mf][nf][2] + b0, acc[mf][nf][3] + b1);
        }
    }
}

// ---------------------------------------------------------------------------
// Persistent recurrence via fp16 HMMA — round-11 proven structure: 64-k
// chunks, 4-stage cp.async pipeline, split Bh/Bl accumulators, register
// epilogue. Only delta vs round 11: no fp32 g_h2 store (fc reads fp16).
// SMEM map (bytes):
//   0       sWh [32][1032 f16] (pitch 2064)
//   66048   sWl
//   132096  sA stages 0..3, each [64][72 f16] (9216 B)
// total 168960
// ---------------------------------------------------------------------------
#define LW_PITCHB 2064
#define LA_PITCHB 144
#define LA_STAGEB 9216
#define LS_SMEM   168960

__device__ __forceinline__ void la_load(unsigned dst, const __half* hsrc,
                                        size_t hstr, int k0, int tid)
{
#pragma unroll
    for (int i = 0; i < 2; i++) {
        int u = tid + 256 * i;       // 0..511
        int rr = u >> 3;             // 0..63
        int cc = u & 7;
        cp16(dst + rr * LA_PITCHB + cc * 16, hsrc + (size_t)rr * hstr + k0 + cc * 8);
    }
}

__global__ void __launch_bounds__(256, 1)
lstm_mma_kernel(int layer, const float* __restrict__ c0l)
{
    extern __shared__ char sm[];
    unsigned sb = smem_u32(sm);

    const __half* __restrict__ Wh = layer ? g_W1h : g_W0h;
    const __half* __restrict__ Wl = layer ? g_W1l : g_W0l;
    __half* __restrict__ seqf     = layer ? g_h2f : g_h1f;

    int tid  = threadIdx.x;
    int lane = tid & 31;
    int w    = tid >> 5;
    int n0   = blockIdx.x * 32;
    int j0   = blockIdx.x * 8;

    // one-time W load (hi/lo)
    {
        const unsigned* srcH = (const unsigned*)(Wh + (size_t)n0 * Hv);
        const unsigned* srcL = (const unsigned*)(Wl + (size_t)n0 * Hv);
        unsigned* dH = (unsigned*)sm;
        unsigned* dL = (unsigned*)(sm + 66048);
        for (int i = tid; i < 32 * 512; i += 256) {
            int r = i >> 9, cc = i & 511;
            dH[r * 516 + cc] = srcH[r * 512 + cc];
            dL[r * 516 + cc] = srcL[r * 512 + cc];
        }
    }
    __syncthreads();

    int wm = w & 1, wn = w >> 1;
    int jl = 2 * wn + ((lane & 3) >> 1);
    bool evn = ((lane & 1) == 0);

    float c_[4];
#pragma unroll
    for (int mf = 0; mf < 2; mf++)
#pragma unroll
        for (int rr = 0; rr < 2; rr++) {
            int b = 32 * wm + 16 * mf + (lane >> 2) + 8 * rr;
            c_[mf * 2 + rr] = c0l[(size_t)b * Hv + j0 + jl];
        }

    unsigned aoff  = (unsigned)((32 * wm + (lane & 15)) * LA_PITCHB + ((lane & 16) ? 16 : 0));
    int rl = lane & 15;
    unsigned boffH = sb + (unsigned)((8 * wn + (rl & 7)) * LW_PITCHB + ((rl & 8) ? 16 : 0));
    unsigned boffL = boffH + 66048;
    unsigned sAb = sb + 132096;

    unsigned lg = g_bar_gen;

    for (int t = 0; t < Tv; t++) {
        const __half* hsrc;
        size_t hstr;
        if (t == 0) {
            hsrc = g_h0s + layer * (Bv * Hv);
            hstr = Hv;
        } else {
            hsrc = seqf + (size_t)(t - 1) * Hv;
            hstr = (size_t)Tv * Hv;
        }

        // prologue: 3 chunks in flight
        la_load(sAb,                 hsrc, hstr, 0,   tid); CP_COMMIT();
        la_load(sAb + LA_STAGEB,     hsrc, hstr, 64,  tid); CP_COMMIT();
        la_load(sAb + 2 * LA_STAGEB, hsrc, hstr, 128, tid); CP_COMMIT();

        float4 xgv[4];
#pragma unroll
        for (int mf = 0; mf < 2; mf++)
#pragma unroll
            for (int rr = 0; rr < 2; rr++) {
                int b = 32 * wm + 16 * mf + (lane >> 2) + 8 * rr;
                xgv[mf * 2 + rr] = *(const float4*)&g_xg[((size_t)b * Tv + t) * Gv + n0 + 4 * jl];
            }

        float accH[2][4], accL[2][4];
#pragma unroll
        for (int mf = 0; mf < 2; mf++)
#pragma unroll
            for (int e = 0; e < 4; e++) { accH[mf][e] = 0.f; accL[mf][e] = 0.f; }

        for (int ch = 0; ch < 16; ch++) {
            unsigned ab = sAb + (ch & 3) * LA_STAGEB;
            if (ch <= 13)      { CP_WAIT2(); }
            else if (ch == 14) { CP_WAIT1(); }
            else               { CP_WAIT0(); }
            __syncthreads();

            if (ch + 3 < 16) {
                la_load(sAb + ((ch + 3) & 3) * LA_STAGEB, hsrc, hstr, (ch + 3) * 64, tid);
                CP_COMMIT();
            }

#pragma unroll
            for (int ks = 0; ks < 4; ks++) {
                unsigned kb = (unsigned)(ks * 32);
                unsigned wkb = (unsigned)((ch * 64 + ks * 16) * 2);
                unsigned Ahf[2][4], Bhf[2], Blf[2];
#pragma unroll
                for (int mf = 0; mf < 2; mf++)
                    ldm_x4(Ahf[mf], ab + aoff + kb + (unsigned)(16 * mf * LA_PITCHB));
                ldm_x2(Bhf, boffH + wkb);
                ldm_x2(Blf, boffL + wkb);
#pragma unroll
                for (int mf = 0; mf < 2; mf++) {
                    mma16816f(accH[mf], Ahf[mf], Bhf);
                    mma16816f(accL[mf], Ahf[mf], Blf);
                }
            }
        }

        // combine hi/lo accumulators
        float acc[2][4];
#pragma unroll
        for (int mf = 0; mf < 2; mf++)
#pragma unroll
            for (int e = 0; e < 4; e++) acc[mf][e] = accH[mf][e] + accL[mf][e];

        // register epilogue: pair lanes exchange (i,f)<->(g,o)
        float pr[2][4];
#pragma unroll
        for (int mf = 0; mf < 2; mf++)
#pragma unroll
            for (int e = 0; e < 4; e++)
                pr[mf][e] = __shfl_xor_sync(0xFFFFFFFFu, acc[mf][e], 1);

#pragma unroll
        for (int mf = 0; mf < 2; mf++) {
#pragma unroll
            for (int rr = 0; rr < 2; rr++) {
                int ci = mf * 2 + rr;
                int b = 32 * wm + 16 * mf + (lane >> 2) + 8 * rr;
                float iv, fv, gv, ov;
                if (evn) { iv = acc[mf][2 * rr]; fv = acc[mf][2 * rr + 1];
                           gv = pr[mf][2 * rr];  ov = pr[mf][2 * rr + 1]; }
                else     { iv = pr[mf][2 * rr];  fv = pr[mf][2 * rr + 1];
                           gv = acc[mf][2 * rr]; ov = acc[mf][2 * rr + 1]; }
                float4 xg = xgv[ci];
                float i_ = sigf(iv + xg.x);
                float f_ = sigf(fv + xg.y);
                float g_ = tanhf(gv + xg.z);
                float o_ = sigf(ov + xg.w);
                float c = f_ * c_[ci] + i_ * g_;
                c_[ci] = c;
                float h = o_ * tanhf(c);
                if (evn) {
                    size_t idx = ((size_t)b * Tv + t) * Hv + j0 + jl;
                    seqf[idx] = __float2half_rn(h);
                }
            }
        }

        if (t != Tv - 1) grid_barrier(lg);
    }
}

// ---------------------------------------------------------------------------
// Final FC — reads fp16 h2 directly.
// ---------------------------------------------------------------------------
__global__ void fc_kernel(const float* __restrict__ Wfc, const float* __restrict__ bfc,
                          float* __restrict__ out)
{
    int bt = blockIdx.x * 8 + (threadIdx.x >> 5);
    int lane = threadIdx.x & 31;
    const __half2* hrow = (const __half2*)(g_h2f + (size_t)bt * Hv);
    float s = 0.f;
#pragma unroll 4
    for (int k = lane; k < Hv / 2; k += 32) {
        float2 h2 = __half22float2(hrow[k]);
        s += h2.x * Wfc[2 * k] + h2.y * Wfc[2 * k + 1];
    }
#pragma unroll
    for (int off = 16; off; off >>= 1) s += __shfl_down_sync(0xFFFFFFFFu, s, off);
    if (lane == 0) out[bt] = s + bfc[0];
}

// ---------------------------------------------------------------------------
// Launch (6 graph nodes)
// ---------------------------------------------------------------------------
extern "C" void kernel_launch(void* const* d_in, const int* in_sizes, int n_in,
                              void* d_out, int out_size)
{
    (void)in_sizes; (void)n_in; (void)out_size;
    const float* x    = (const float*)d_in[0];
    const float* h0   = (const float*)d_in[1];
    const float* c0   = (const float*)d_in[2];
    const float* Wih0 = (const float*)d_in[3];
    const float* Whh0 = (const float*)d_in[4];
    const float* bih0 = (const float*)d_in[5];
    const float* bhh0 = (const float*)d_in[6];
    const float* Wih1 = (const float*)d_in[7];
    const float* Whh1 = (const float*)d_in[8];
    const float* bih1 = (const float*)d_in[9];
    const float* bhh1 = (const float*)d_in[10];
    const float* Wfc  = (const float*)d_in[11];
    const float* bfc  = (const float*)d_in[12];
    float* out = (float*)d_out;

    cudaFuncSetAttribute(lstm_mma_kernel,
                         cudaFuncAttributeMaxDynamicSharedMemorySize, LS_SMEM);
    cudaFuncSetAttribute(proj_mma_kernel<Iv>,
                         cudaFuncAttributeMaxDynamicSharedMemorySize, PJ_SMEM);
    cudaFuncSetAttribute(proj_mma_kernel<Hv>,
                         cudaFuncAttributeMaxDynamicSharedMemorySize, PJ_SMEM);

    prep_kernel<<<2048, 256>>>(Whh0, Whh1, Wih0, Wih1, bih0, bhh0, bih1, bhh1, h0, x);

    // Layer 0: HMMA projection (K=128) + recurrence
    proj_mma_kernel<Iv><<<dim3(Gv / 128, BTv / 128), 256, PJ_SMEM>>>();
    lstm_mma_kernel<<<NBLK, 256, LS_SMEM>>>(0, c0);

    // Layer 1: HMMA projection (K=1024) + recurrence
    proj_mma_kernel<Hv><<<dim3(Gv / 128, BTv / 128), 256, PJ_SMEM>>>();
    lstm_mma_kernel<<<NBLK, 256, LS_SMEM>>>(1, c0 + (size_t)Bv * Hv);

    fc_kernel<<<BTv / 8, 256>>>(Wfc, bfc, out);
}